// round 3
// baseline (speedup 1.0000x reference)
#include <cuda_runtime.h>

#define N_IMG 8
#define HH 128
#define WW 128
#define CF 64

// Scratch buffers (allocation-free workaround per harness rules)
__device__ float g_H[N_IMG * CF * HH * WW];          // head output / skip / body result
__device__ float g_A[N_IMG * CF * HH * WW];          // resblock carry
__device__ float g_B[N_IMG * CF * HH * WW];          // resblock temp
__device__ float g_S[N_IMG * 100 * 256 * 256];       // pixel-shuffled super output

// ---------------------------------------------------------------------------
// Head: out = conv3x3(x - mean, head_w) + head_b      (3 -> 64 channels)
// ---------------------------------------------------------------------------
__global__ __launch_bounds__(256) void head_kernel(
    const float* __restrict__ x, const float* __restrict__ w,
    const float* __restrict__ b, float* __restrict__ out)
{
    int idx = blockIdx.x * 256 + threadIdx.x;
    if (idx >= N_IMG * CF * HH * WW) return;
    int px = idx & (WW - 1);
    int py = (idx >> 7) & (HH - 1);
    int oc = (idx >> 14) & 63;
    int n  = idx >> 20;

    const float mean[3] = {0.4488f * 255.0f, 0.4371f * 255.0f, 0.404f * 255.0f};
    float acc = b[oc];
    #pragma unroll
    for (int ic = 0; ic < 3; ic++) {
        const float* xin = x + ((n * 3 + ic) * HH) * WW;
        const float* wp  = w + (oc * 3 + ic) * 9;
        #pragma unroll
        for (int dy = 0; dy < 3; dy++) {
            int gy = py + dy - 1;
            if ((unsigned)gy >= HH) continue;
            #pragma unroll
            for (int dx = 0; dx < 3; dx++) {
                int gx = px + dx - 1;
                if ((unsigned)gx >= WW) continue;
                acc += (xin[gy * WW + gx] - mean[ic]) * wp[dy * 3 + dx];
            }
        }
    }
    out[idx] = acc;
}

// ---------------------------------------------------------------------------
// Main 3x3 conv, CIN=64, 64-oc chunk per block.
// Block = 128 threads, computes 64 oc x (16w x 8h) pixel tile.
// Thread = 4 oc x 16 px (one full-width tile row) register tile.
//   tid = oc_thr*8 + ty ; oc_thr in 0..15 owns 4 oc ; ty in 0..7 owns row.
// Per (icl,dy) inner step: 72B input + 48B weights per 192 FMA-lanes
//   -> ~0.63 B/FMA, below the 128 B/cyc/SM LDS crossbar ceiling at full FMA.
// ---------------------------------------------------------------------------
template <bool RELU, bool RES, bool SHUF>
__global__ __launch_bounds__(128) void conv3x3_64(
    const float* __restrict__ in, const float* __restrict__ w,
    const float* __restrict__ bias, const float* __restrict__ res,
    float* __restrict__ out, int cout_total, int oc_chunks)
{
    __shared__ float in_s[8][10][20];     // 8 ic x (8+2) rows x (16+2, pad 20) cols
    __shared__ float w_s[72][64];         // (8 ic * 9 taps) x 64 oc

    const int tid     = threadIdx.x;
    const int n       = blockIdx.z / oc_chunks;
    const int oc_base = (blockIdx.z % oc_chunks) * 64;
    const int x0      = blockIdx.x * 16;
    const int y0      = blockIdx.y * 8;
    const int oc_thr  = tid >> 3;         // 0..15 -> owns 4 oc
    const int ty      = tid & 7;          // 0..7  -> owns one 16-wide row

    float acc[4][16];
    #pragma unroll
    for (int o = 0; o < 4; o++)
        #pragma unroll
        for (int j = 0; j < 16; j++) acc[o][j] = 0.f;

    for (int ic0 = 0; ic0 < 64; ic0 += 8) {
        // cooperative input tile load (zero-padded halo), 1440 elems
        for (int idx = tid; idx < 8 * 10 * 18; idx += 128) {
            int icl = idx / 180;
            int rem = idx - icl * 180;
            int r = rem / 18;
            int c = rem - r * 18;
            int gy = y0 + r - 1;
            int gx = x0 + c - 1;
            float v = 0.f;
            if ((unsigned)gy < HH && (unsigned)gx < WW)
                v = in[((n * 64 + ic0 + icl) * HH + gy) * WW + gx];
            in_s[icl][r][c] = v;
        }
        // cooperative weight load, transposed to [k][oc]
        for (int idx = tid; idx < 72 * 64; idx += 128) {
            int k   = idx >> 6;
            int oc  = idx & 63;
            int icl = k / 9;
            int tap = k - icl * 9;
            int ocg = oc_base + oc;
            float v = 0.f;
            if (ocg < cout_total)
                v = w[(ocg * 64 + ic0 + icl) * 9 + tap];
            w_s[k][oc] = v;
        }
        __syncthreads();

        #pragma unroll 2
        for (int icl = 0; icl < 8; icl++) {
            #pragma unroll
            for (int dy = 0; dy < 3; dy++) {
                const float* row = &in_s[icl][ty + dy][0];
                float rv[18];
                #pragma unroll
                for (int q = 0; q < 4; q++) {
                    float4 t = *(const float4*)(row + q * 4);
                    rv[q * 4 + 0] = t.x; rv[q * 4 + 1] = t.y;
                    rv[q * 4 + 2] = t.z; rv[q * 4 + 3] = t.w;
                }
                rv[16] = row[16];
                rv[17] = row[17];
                #pragma unroll
                for (int dx = 0; dx < 3; dx++) {
                    float4 wv = *(const float4*)&w_s[icl * 9 + dy * 3 + dx][oc_thr * 4];
                    #pragma unroll
                    for (int j = 0; j < 16; j++) {
                        float iv = rv[j + dx];
                        acc[0][j] += wv.x * iv;
                        acc[1][j] += wv.y * iv;
                        acc[2][j] += wv.z * iv;
                        acc[3][j] += wv.w * iv;
                    }
                }
            }
        }
        __syncthreads();
    }

    // epilogue
    const int yy = y0 + ty;
    #pragma unroll
    for (int o = 0; o < 4; o++) {
        int oc = oc_base + oc_thr * 4 + o;
        if (oc >= cout_total) continue;
        float bv = bias[oc];
        if (SHUF) {
            int k = oc >> 2;
            int a = (oc >> 1) & 1;
            int bb = oc & 1;
            float* op = out + ((n * 100 + k) * 256 + (yy * 2 + a)) * 256 + bb;
            #pragma unroll
            for (int j = 0; j < 16; j++) {
                float v = acc[o][j] + bv;
                if (RELU) v = fmaxf(v, 0.f);
                op[(x0 + j) * 2] = v;
            }
        } else {
            float* op = out + ((n * 64 + oc) * HH + yy) * WW + x0;
            const float* rp = RES ? res + ((n * 64 + oc) * HH + yy) * WW + x0 : nullptr;
            #pragma unroll
            for (int q = 0; q < 4; q++) {
                float4 v;
                v.x = acc[o][q * 4 + 0] + bv;
                v.y = acc[o][q * 4 + 1] + bv;
                v.z = acc[o][q * 4 + 2] + bv;
                v.w = acc[o][q * 4 + 3] + bv;
                if (RELU) {
                    v.x = fmaxf(v.x, 0.f); v.y = fmaxf(v.y, 0.f);
                    v.z = fmaxf(v.z, 0.f); v.w = fmaxf(v.w, 0.f);
                }
                if (RES) {
                    float4 r4 = *(const float4*)(rp + q * 4);
                    v.x += r4.x; v.y += r4.y; v.z += r4.z; v.w += r4.w;
                }
                *(float4*)(op + q * 4) = v;
            }
        }
    }
}

// ---------------------------------------------------------------------------
// Tail: y = conv3x3(shuffled, out_w) + out_b + mean    (100 -> 3, 256x256)
// ---------------------------------------------------------------------------
__global__ __launch_bounds__(256) void tail_kernel(
    const float* __restrict__ in, const float* __restrict__ w,
    const float* __restrict__ b, float* __restrict__ out)
{
    __shared__ float w_s[2700];   // [3][100][9]
    for (int i = threadIdx.x; i < 2700; i += 256) w_s[i] = w[i];
    __syncthreads();

    int idx = blockIdx.x * 256 + threadIdx.x;   // over N*256*256
    int x = idx & 255;
    int y = (idx >> 8) & 255;
    int n = idx >> 16;

    float a0 = b[0], a1 = b[1], a2 = b[2];
    for (int ic = 0; ic < 100; ic++) {
        const float* ip = in + ((n * 100 + ic) * 256) * 256;
        #pragma unroll
        for (int dy = 0; dy < 3; dy++) {
            int gy = y + dy - 1;
            if ((unsigned)gy >= 256) continue;
            #pragma unroll
            for (int dx = 0; dx < 3; dx++) {
                int gx = x + dx - 1;
                if ((unsigned)gx >= 256) continue;
                float v = ip[gy * 256 + gx];
                int t = ic * 9 + dy * 3 + dx;
                a0 += v * w_s[t];
                a1 += v * w_s[900 + t];
                a2 += v * w_s[1800 + t];
            }
        }
    }
    const float m0 = 0.4488f * 255.0f, m1 = 0.4371f * 255.0f, m2 = 0.404f * 255.0f;
    out[((n * 3 + 0) * 256 + y) * 256 + x] = a0 + m0;
    out[((n * 3 + 1) * 256 + y) * 256 + x] = a1 + m1;
    out[((n * 3 + 2) * 256 + y) * 256 + x] = a2 + m2;
}

// ---------------------------------------------------------------------------
extern "C" void kernel_launch(void* const* d_in, const int* in_sizes, int n_in,
                              void* d_out, int out_size)
{
    const float* x       = (const float*)d_in[0];
    const float* head_w  = (const float*)d_in[1];
    const float* head_b  = (const float*)d_in[2];
    const float* rb_w1   = (const float*)d_in[3];
    const float* rb_b1   = (const float*)d_in[4];
    const float* rb_w2   = (const float*)d_in[5];
    const float* rb_b2   = (const float*)d_in[6];
    const float* body_w  = (const float*)d_in[7];
    const float* body_b  = (const float*)d_in[8];
    const float* super_w = (const float*)d_in[9];
    const float* super_b = (const float*)d_in[10];
    const float* out_w   = (const float*)d_in[11];
    const float* out_b   = (const float*)d_in[12];
    float* out = (float*)d_out;

    float *pH, *pA, *pB, *pS;
    cudaGetSymbolAddress((void**)&pH, g_H);
    cudaGetSymbolAddress((void**)&pA, g_A);
    cudaGetSymbolAddress((void**)&pB, g_B);
    cudaGetSymbolAddress((void**)&pS, g_S);

    // head
    head_kernel<<<(N_IMG * CF * HH * WW) / 256, 256>>>(x, head_w, head_b, pH);

    dim3 grid(WW / 16, HH / 8, N_IMG);

    // 16 residual blocks: B = relu(conv1(cur)); A = cur + conv2(B)
    const float* cur = pH;
    for (int i = 0; i < 16; i++) {
        conv3x3_64<true, false, false><<<grid, 128>>>(
            cur, rb_w1 + (size_t)i * 64 * 64 * 9, rb_b1 + i * 64, nullptr, pB, 64, 1);
        conv3x3_64<false, true, false><<<grid, 128>>>(
            pB, rb_w2 + (size_t)i * 64 * 64 * 9, rb_b2 + i * 64, cur, pA, 64, 1);
        cur = pA;
    }

    // body: H = conv(A) + H   (in-place residual on H is safe: H not conv input)
    conv3x3_64<false, true, false><<<grid, 128>>>(pA, body_w, body_b, pH, pH, 64, 1);

    // super conv 64 -> 400 with fused pixel shuffle (7 oc-chunks of 64)
    dim3 gridS(WW / 16, HH / 8, N_IMG * 7);
    conv3x3_64<false, false, true><<<gridS, 128>>>(pH, super_w, super_b, nullptr, pS, 400, 7);

    // tail conv 100 -> 3 on 256x256 + add mean
    tail_kernel<<<(N_IMG * 256 * 256) / 256, 256>>>(pS, out_w, out_b, out);
}

// round 4
// speedup vs baseline: 2.1792x; 2.1792x over previous
#include <cuda_runtime.h>

#define N_IMG 8
#define HH 128
#define WW 128
#define CF 64

typedef unsigned long long ull;

// Scratch buffers (allocation-free workaround per harness rules)
__device__ float g_H[N_IMG * CF * HH * WW];
__device__ float g_A[N_IMG * CF * HH * WW];
__device__ float g_B[N_IMG * CF * HH * WW];
__device__ float g_S[N_IMG * 100 * 256 * 256];

// Pre-transposed weights: per 64-oc chunk, layout [8 stages][72 k][64 oc]
#define WCHUNK (8 * 72 * 64)
__device__ float g_W1[16 * WCHUNK];
__device__ float g_W2[16 * WCHUNK];
__device__ float g_WB[WCHUNK];
__device__ float g_WS[7 * WCHUNK];

__device__ __forceinline__ ull pk2(float lo, float hi) {
    ull r; asm("mov.b64 %0, {%1, %2};" : "=l"(r) : "f"(lo), "f"(hi)); return r;
}
__device__ __forceinline__ void upk2(ull v, float& lo, float& hi) {
    asm("mov.b64 {%0, %1}, %2;" : "=f"(lo), "=f"(hi) : "l"(v));
}
#define FMA2(d, a, b) asm("fma.rn.f32x2 %0, %1, %2, %0;" : "+l"(d) : "l"(a), "l"(b))

// ---------------------------------------------------------------------------
// Weight reformat: src [cout][64][9] (per conv) -> dst [nchunks][8][72][64]
// ---------------------------------------------------------------------------
__global__ __launch_bounds__(256) void reformat_w(
    const float* __restrict__ src, float* __restrict__ dst,
    int cout, int src_conv_stride)
{
    int conv = blockIdx.z, chunk = blockIdx.y, nchunks = gridDim.y;
    const float* s = src + (size_t)conv * src_conv_stride;
    float* d = dst + ((size_t)conv * nchunks + chunk) * WCHUNK;
    int idx = blockIdx.x * 256 + threadIdx.x;
    if (idx >= WCHUNK) return;
    int st = idx / 4608;
    int r  = idx - st * 4608;
    int k  = r >> 6;
    int oc = r & 63;
    int icl = k / 9;
    int tap = k - icl * 9;
    int ic  = st * 8 + icl;
    int ocg = chunk * 64 + oc;
    d[idx] = (ocg < cout) ? s[(ocg * 64 + ic) * 9 + tap] : 0.f;
}

// ---------------------------------------------------------------------------
// Head: out = conv3x3(x - mean, head_w) + head_b      (3 -> 64 channels)
// ---------------------------------------------------------------------------
__global__ __launch_bounds__(256) void head_kernel(
    const float* __restrict__ x, const float* __restrict__ w,
    const float* __restrict__ b, float* __restrict__ out)
{
    int idx = blockIdx.x * 256 + threadIdx.x;
    if (idx >= N_IMG * CF * HH * WW) return;
    int px = idx & (WW - 1);
    int py = (idx >> 7) & (HH - 1);
    int oc = (idx >> 14) & 63;
    int n  = idx >> 20;

    const float mean[3] = {0.4488f * 255.0f, 0.4371f * 255.0f, 0.404f * 255.0f};
    float acc = b[oc];
    #pragma unroll
    for (int ic = 0; ic < 3; ic++) {
        const float* xin = x + ((n * 3 + ic) * HH) * WW;
        const float* wp  = w + (oc * 3 + ic) * 9;
        #pragma unroll
        for (int dy = 0; dy < 3; dy++) {
            int gy = py + dy - 1;
            if ((unsigned)gy >= HH) continue;
            #pragma unroll
            for (int dx = 0; dx < 3; dx++) {
                int gx = px + dx - 1;
                if ((unsigned)gx >= WW) continue;
                acc += (xin[gy * WW + gx] - mean[ic]) * wp[dy * 3 + dx];
            }
        }
    }
    out[idx] = acc;
}

// ---------------------------------------------------------------------------
// Main 3x3 conv, CIN=64. Block = 128 thr = 64 oc x (16w x 8h) tile.
// Thread = 4 oc x 16 px, pixels packed in f32x2 pairs -> fma.rn.f32x2.
// dx=0/2 taps read aligned pairs of in_s; dx=1 reads a 1-shifted copy in_s2.
// Weights pre-transposed -> pure coalesced float4 copy into smem.
// ---------------------------------------------------------------------------
template <bool RELU, bool RES, bool SHUF>
__global__ __launch_bounds__(128) void conv3x3_64(
    const float* __restrict__ in, const float* __restrict__ w,
    const float* __restrict__ bias, const float* __restrict__ res,
    float* __restrict__ out, int cout_total, int oc_chunks)
{
    __shared__ float in_s [8][10][20];   // 18 valid cols (halo), pitch 20
    __shared__ float in_s2[8][10][20];   // shifted by +1 col (17 valid)
    __shared__ float w_s[72 * 64];       // [k][oc], same layout as prepped gmem

    const int tid     = threadIdx.x;
    const int n       = blockIdx.z / oc_chunks;
    const int chunk   = blockIdx.z % oc_chunks;
    const int oc_base = chunk * 64;
    const int x0      = blockIdx.x * 16;
    const int y0      = blockIdx.y * 8;
    const int oc_thr  = tid >> 3;        // 0..15 -> 4 oc
    const int ty      = tid & 7;         // 0..7  -> one 16-wide row

    const float* wbase = w + (size_t)chunk * WCHUNK;

    ull acc[4][8];
    #pragma unroll
    for (int o = 0; o < 4; o++)
        #pragma unroll
        for (int q = 0; q < 8; q++) acc[o][q] = pk2(0.f, 0.f);

    for (int st = 0; st < 8; st++) {
        // input tile (+ shifted copy), zero-padded halo
        for (int idx = tid; idx < 8 * 10 * 18; idx += 128) {
            int icl = idx / 180;
            int rem = idx - icl * 180;
            int r = rem / 18;
            int c = rem - r * 18;
            int gy = y0 + r - 1;
            int gx = x0 + c - 1;
            float v = 0.f;
            if ((unsigned)gy < HH && (unsigned)gx < WW)
                v = in[((n * 64 + st * 8 + icl) * HH + gy) * WW + gx];
            in_s[icl][r][c] = v;
            if (c >= 1) in_s2[icl][r][c - 1] = v;
        }
        // weights: coalesced float4 copy (prepped layout == smem layout)
        {
            const float4* ws4 = (const float4*)(wbase + st * 4608);
            float4* wd4 = (float4*)w_s;
            #pragma unroll
            for (int i = 0; i < 9; i++)
                wd4[tid + i * 128] = ws4[tid + i * 128];
        }
        __syncthreads();

        #pragma unroll 1
        for (int icl = 0; icl < 8; icl++) {
            #pragma unroll
            for (int dy = 0; dy < 3; dy++) {
                const float* row0 = &in_s [icl][ty + dy][0];
                const float* rowS = &in_s2[icl][ty + dy][0];
                const int kb = icl * 9 + dy * 3;

                float4 w0 = *(const float4*)&w_s[(kb + 0) * 64 + oc_thr * 4];
                float4 w1 = *(const float4*)&w_s[(kb + 1) * 64 + oc_thr * 4];
                float4 w2 = *(const float4*)&w_s[(kb + 2) * 64 + oc_thr * 4];
                ull wd0[4] = {pk2(w0.x,w0.x), pk2(w0.y,w0.y), pk2(w0.z,w0.z), pk2(w0.w,w0.w)};
                ull wd1[4] = {pk2(w1.x,w1.x), pk2(w1.y,w1.y), pk2(w1.z,w1.z), pk2(w1.w,w1.w)};
                ull wd2[4] = {pk2(w2.x,w2.x), pk2(w2.y,w2.y), pk2(w2.z,w2.z), pk2(w2.w,w2.w)};

                #pragma unroll
                for (int q = 0; q < 8; q++) {
                    ull iv0 = *(const ull*)(row0 + 2 * q);        // (rv[2q],   rv[2q+1])
                    ull iv1 = *(const ull*)(rowS + 2 * q);        // (rv[2q+1], rv[2q+2])
                    ull iv2 = *(const ull*)(row0 + 2 * q + 2);    // (rv[2q+2], rv[2q+3])
                    #pragma unroll
                    for (int o = 0; o < 4; o++) {
                        FMA2(acc[o][q], wd0[o], iv0);
                        FMA2(acc[o][q], wd1[o], iv1);
                        FMA2(acc[o][q], wd2[o], iv2);
                    }
                }
            }
        }
        __syncthreads();
    }

    // epilogue
    const int yy = y0 + ty;
    #pragma unroll
    for (int o = 0; o < 4; o++) {
        int oc = oc_base + oc_thr * 4 + o;
        if (oc >= cout_total) continue;
        float bv = bias[oc];
        if (SHUF) {
            int k = oc >> 2;
            int a = (oc >> 1) & 1;
            int bb = oc & 1;
            float* op = out + ((n * 100 + k) * 256 + (yy * 2 + a)) * 256 + bb;
            #pragma unroll
            for (int q = 0; q < 8; q++) {
                float v0, v1;
                upk2(acc[o][q], v0, v1);
                v0 += bv; v1 += bv;
                if (RELU) { v0 = fmaxf(v0, 0.f); v1 = fmaxf(v1, 0.f); }
                op[(x0 + 2 * q)     * 2] = v0;
                op[(x0 + 2 * q + 1) * 2] = v1;
            }
        } else {
            float* op = out + ((n * 64 + oc) * HH + yy) * WW + x0;
            const float* rp = RES ? res + ((n * 64 + oc) * HH + yy) * WW + x0 : nullptr;
            #pragma unroll
            for (int q = 0; q < 8; q++) {
                float v0, v1;
                upk2(acc[o][q], v0, v1);
                v0 += bv; v1 += bv;
                if (RELU) { v0 = fmaxf(v0, 0.f); v1 = fmaxf(v1, 0.f); }
                if (RES) {
                    float2 r2 = *(const float2*)(rp + 2 * q);
                    v0 += r2.x; v1 += r2.y;
                }
                float2 v; v.x = v0; v.y = v1;
                *(float2*)(op + 2 * q) = v;
            }
        }
    }
}

// ---------------------------------------------------------------------------
// Tail: y = conv3x3(shuffled, out_w) + out_b + mean    (100 -> 3, 256x256)
// ---------------------------------------------------------------------------
__global__ __launch_bounds__(256) void tail_kernel(
    const float* __restrict__ in, const float* __restrict__ w,
    const float* __restrict__ b, float* __restrict__ out)
{
    __shared__ float w_s[2700];
    for (int i = threadIdx.x; i < 2700; i += 256) w_s[i] = w[i];
    __syncthreads();

    int idx = blockIdx.x * 256 + threadIdx.x;
    int x = idx & 255;
    int y = (idx >> 8) & 255;
    int n = idx >> 16;

    float a0 = b[0], a1 = b[1], a2 = b[2];
    for (int ic = 0; ic < 100; ic++) {
        const float* ip = in + ((n * 100 + ic) * 256) * 256;
        #pragma unroll
        for (int dy = 0; dy < 3; dy++) {
            int gy = y + dy - 1;
            if ((unsigned)gy >= 256) continue;
            #pragma unroll
            for (int dx = 0; dx < 3; dx++) {
                int gx = x + dx - 1;
                if ((unsigned)gx >= 256) continue;
                float v = ip[gy * 256 + gx];
                int t = ic * 9 + dy * 3 + dx;
                a0 += v * w_s[t];
                a1 += v * w_s[900 + t];
                a2 += v * w_s[1800 + t];
            }
        }
    }
    const float m0 = 0.4488f * 255.0f, m1 = 0.4371f * 255.0f, m2 = 0.404f * 255.0f;
    out[((n * 3 + 0) * 256 + y) * 256 + x] = a0 + m0;
    out[((n * 3 + 1) * 256 + y) * 256 + x] = a1 + m1;
    out[((n * 3 + 2) * 256 + y) * 256 + x] = a2 + m2;
}

// ---------------------------------------------------------------------------
extern "C" void kernel_launch(void* const* d_in, const int* in_sizes, int n_in,
                              void* d_out, int out_size)
{
    const float* x       = (const float*)d_in[0];
    const float* head_w  = (const float*)d_in[1];
    const float* head_b  = (const float*)d_in[2];
    const float* rb_w1   = (const float*)d_in[3];
    const float* rb_b1   = (const float*)d_in[4];
    const float* rb_w2   = (const float*)d_in[5];
    const float* rb_b2   = (const float*)d_in[6];
    const float* body_w  = (const float*)d_in[7];
    const float* body_b  = (const float*)d_in[8];
    const float* super_w = (const float*)d_in[9];
    const float* super_b = (const float*)d_in[10];
    const float* out_w   = (const float*)d_in[11];
    const float* out_b   = (const float*)d_in[12];
    float* out = (float*)d_out;

    float *pH, *pA, *pB, *pS, *pW1, *pW2, *pWB, *pWS;
    cudaGetSymbolAddress((void**)&pH, g_H);
    cudaGetSymbolAddress((void**)&pA, g_A);
    cudaGetSymbolAddress((void**)&pB, g_B);
    cudaGetSymbolAddress((void**)&pS, g_S);
    cudaGetSymbolAddress((void**)&pW1, g_W1);
    cudaGetSymbolAddress((void**)&pW2, g_W2);
    cudaGetSymbolAddress((void**)&pWB, g_WB);
    cudaGetSymbolAddress((void**)&pWS, g_WS);

    // weight reformat (tiny)
    dim3 rg(144, 1, 16);
    reformat_w<<<rg, 256>>>(rb_w1, pW1, 64, 64 * 64 * 9);
    reformat_w<<<rg, 256>>>(rb_w2, pW2, 64, 64 * 64 * 9);
    reformat_w<<<dim3(144, 1, 1), 256>>>(body_w, pWB, 64, 0);
    reformat_w<<<dim3(144, 7, 1), 256>>>(super_w, pWS, 400, 0);

    // head
    head_kernel<<<(N_IMG * CF * HH * WW) / 256, 256>>>(x, head_w, head_b, pH);

    dim3 grid(WW / 16, HH / 8, N_IMG);

    // 16 residual blocks: B = relu(conv1(cur)); A = cur + conv2(B)
    const float* cur = pH;
    for (int i = 0; i < 16; i++) {
        conv3x3_64<true, false, false><<<grid, 128>>>(
            cur, pW1 + (size_t)i * WCHUNK, rb_b1 + i * 64, nullptr, pB, 64, 1);
        conv3x3_64<false, true, false><<<grid, 128>>>(
            pB, pW2 + (size_t)i * WCHUNK, rb_b2 + i * 64, cur, pA, 64, 1);
        cur = pA;
    }

    // body: H = conv(A) + H
    conv3x3_64<false, true, false><<<grid, 128>>>(pA, pWB, body_b, pH, pH, 64, 1);

    // super conv 64 -> 400 with fused pixel shuffle (7 oc-chunks of 64)
    dim3 gridS(WW / 16, HH / 8, N_IMG * 7);
    conv3x3_64<false, false, true><<<gridS, 128>>>(pH, pWS, super_b, nullptr, pS, 400, 7);

    // tail conv 100 -> 3 on 256x256 + add mean
    tail_kernel<<<(N_IMG * 256 * 256) / 256, 256>>>(pS, out_w, out_b, out);
}

// round 5
// speedup vs baseline: 2.3029x; 1.0567x over previous
#include <cuda_runtime.h>

#define N_IMG 8
#define HH 128
#define WW 128
#define CF 64

typedef unsigned long long ull;

// Scratch buffers (allocation-free workaround per harness rules)
__device__ float g_H[N_IMG * CF * HH * WW];
__device__ float g_A[N_IMG * CF * HH * WW];
__device__ float g_B[N_IMG * CF * HH * WW];
__device__ float g_S[N_IMG * 100 * 256 * 256];

// Pre-transposed weights: per 64-oc chunk, layout [8 stages][72 k][64 oc]
#define WCHUNK (8 * 72 * 64)
__device__ float g_W1[16 * WCHUNK];
__device__ float g_W2[16 * WCHUNK];
__device__ float g_WB[WCHUNK];
__device__ float g_WS[7 * WCHUNK];

__device__ __forceinline__ ull pk2(float lo, float hi) {
    ull r; asm("mov.b64 %0, {%1, %2};" : "=l"(r) : "f"(lo), "f"(hi)); return r;
}
__device__ __forceinline__ void upk2(ull v, float& lo, float& hi) {
    asm("mov.b64 {%0, %1}, %2;" : "=f"(lo), "=f"(hi) : "l"(v));
}
#define FMA2(d, a, b) asm("fma.rn.f32x2 %0, %1, %2, %0;" : "+l"(d) : "l"(a), "l"(b))

// ---------------------------------------------------------------------------
// Weight reformat: src [cout][64][9] (per conv) -> dst [nchunks][8][72][64]
// ---------------------------------------------------------------------------
__global__ __launch_bounds__(256) void reformat_w(
    const float* __restrict__ src, float* __restrict__ dst,
    int cout, int src_conv_stride)
{
    int conv = blockIdx.z, chunk = blockIdx.y, nchunks = gridDim.y;
    const float* s = src + (size_t)conv * src_conv_stride;
    float* d = dst + ((size_t)conv * nchunks + chunk) * WCHUNK;
    int idx = blockIdx.x * 256 + threadIdx.x;
    if (idx >= WCHUNK) return;
    int st = idx / 4608;
    int r  = idx - st * 4608;
    int k  = r >> 6;
    int oc = r & 63;
    int icl = k / 9;
    int tap = k - icl * 9;
    int ic  = st * 8 + icl;
    int ocg = chunk * 64 + oc;
    d[idx] = (ocg < cout) ? s[(ocg * 64 + ic) * 9 + tap] : 0.f;
}

// ---------------------------------------------------------------------------
// Head: out = conv3x3(x - mean, head_w) + head_b      (3 -> 64 channels)
// ---------------------------------------------------------------------------
__global__ __launch_bounds__(256) void head_kernel(
    const float* __restrict__ x, const float* __restrict__ w,
    const float* __restrict__ b, float* __restrict__ out)
{
    int idx = blockIdx.x * 256 + threadIdx.x;
    if (idx >= N_IMG * CF * HH * WW) return;
    int px = idx & (WW - 1);
    int py = (idx >> 7) & (HH - 1);
    int oc = (idx >> 14) & 63;
    int n  = idx >> 20;

    const float mean[3] = {0.4488f * 255.0f, 0.4371f * 255.0f, 0.404f * 255.0f};
    float acc = b[oc];
    #pragma unroll
    for (int ic = 0; ic < 3; ic++) {
        const float* xin = x + ((n * 3 + ic) * HH) * WW;
        const float* wp  = w + (oc * 3 + ic) * 9;
        #pragma unroll
        for (int dy = 0; dy < 3; dy++) {
            int gy = py + dy - 1;
            if ((unsigned)gy >= HH) continue;
            #pragma unroll
            for (int dx = 0; dx < 3; dx++) {
                int gx = px + dx - 1;
                if ((unsigned)gx >= WW) continue;
                acc += (xin[gy * WW + gx] - mean[ic]) * wp[dy * 3 + dx];
            }
        }
    }
    out[idx] = acc;
}

// ---------------------------------------------------------------------------
// Main 3x3 conv, CIN=64. Block = 128 thr = 64 oc x (16w x 8h) tile.
// Thread = 4 oc x 16 px, pixels packed in f32x2 pairs -> fma.rn.f32x2.
// dx=0/2 taps read aligned pairs of in_s; dx=1 reads a 1-shifted copy in_s2.
// Weights pre-transposed -> pure coalesced float4 copy into smem.
// ---------------------------------------------------------------------------
template <bool RELU, bool RES, bool SHUF>
__global__ __launch_bounds__(128) void conv3x3_64(
    const float* __restrict__ in, const float* __restrict__ w,
    const float* __restrict__ bias, const float* __restrict__ res,
    float* __restrict__ out, int cout_total, int oc_chunks)
{
    __shared__ float in_s [8][10][20];   // 18 valid cols (halo), pitch 20
    __shared__ float in_s2[8][10][20];   // shifted by +1 col (17 valid)
    __shared__ float w_s[72 * 64];       // [k][oc], same layout as prepped gmem

    const int tid     = threadIdx.x;
    const int n       = blockIdx.z / oc_chunks;
    const int chunk   = blockIdx.z % oc_chunks;
    const int oc_base = chunk * 64;
    const int x0      = blockIdx.x * 16;
    const int y0      = blockIdx.y * 8;
    const int oc_thr  = tid >> 3;        // 0..15 -> 4 oc
    const int ty      = tid & 7;         // 0..7  -> one 16-wide row

    const float* wbase = w + (size_t)chunk * WCHUNK;

    ull acc[4][8];
    #pragma unroll
    for (int o = 0; o < 4; o++)
        #pragma unroll
        for (int q = 0; q < 8; q++) acc[o][q] = pk2(0.f, 0.f);

    for (int st = 0; st < 8; st++) {
        // input tile (+ shifted copy), zero-padded halo
        for (int idx = tid; idx < 8 * 10 * 18; idx += 128) {
            int icl = idx / 180;
            int rem = idx - icl * 180;
            int r = rem / 18;
            int c = rem - r * 18;
            int gy = y0 + r - 1;
            int gx = x0 + c - 1;
            float v = 0.f;
            if ((unsigned)gy < HH && (unsigned)gx < WW)
                v = in[((n * 64 + st * 8 + icl) * HH + gy) * WW + gx];
            in_s[icl][r][c] = v;
            if (c >= 1) in_s2[icl][r][c - 1] = v;
        }
        // weights: coalesced float4 copy (prepped layout == smem layout)
        {
            const float4* ws4 = (const float4*)(wbase + st * 4608);
            float4* wd4 = (float4*)w_s;
            #pragma unroll
            for (int i = 0; i < 9; i++)
                wd4[tid + i * 128] = ws4[tid + i * 128];
        }
        __syncthreads();

        #pragma unroll 1
        for (int icl = 0; icl < 8; icl++) {
            #pragma unroll
            for (int dy = 0; dy < 3; dy++) {
                const float* row0 = &in_s [icl][ty + dy][0];
                const float* rowS = &in_s2[icl][ty + dy][0];
                const int kb = icl * 9 + dy * 3;

                float4 w0 = *(const float4*)&w_s[(kb + 0) * 64 + oc_thr * 4];
                float4 w1 = *(const float4*)&w_s[(kb + 1) * 64 + oc_thr * 4];
                float4 w2 = *(const float4*)&w_s[(kb + 2) * 64 + oc_thr * 4];
                ull wd0[4] = {pk2(w0.x,w0.x), pk2(w0.y,w0.y), pk2(w0.z,w0.z), pk2(w0.w,w0.w)};
                ull wd1[4] = {pk2(w1.x,w1.x), pk2(w1.y,w1.y), pk2(w1.z,w1.z), pk2(w1.w,w1.w)};
                ull wd2[4] = {pk2(w2.x,w2.x), pk2(w2.y,w2.y), pk2(w2.z,w2.z), pk2(w2.w,w2.w)};

                #pragma unroll
                for (int q = 0; q < 8; q++) {
                    ull iv0 = *(const ull*)(row0 + 2 * q);        // (rv[2q],   rv[2q+1])
                    ull iv1 = *(const ull*)(rowS + 2 * q);        // (rv[2q+1], rv[2q+2])
                    ull iv2 = *(const ull*)(row0 + 2 * q + 2);    // (rv[2q+2], rv[2q+3])
                    #pragma unroll
                    for (int o = 0; o < 4; o++) {
                        FMA2(acc[o][q], wd0[o], iv0);
                        FMA2(acc[o][q], wd1[o], iv1);
                        FMA2(acc[o][q], wd2[o], iv2);
                    }
                }
            }
        }
        __syncthreads();
    }

    // epilogue
    const int yy = y0 + ty;
    #pragma unroll
    for (int o = 0; o < 4; o++) {
        int oc = oc_base + oc_thr * 4 + o;
        if (oc >= cout_total) continue;
        float bv = bias[oc];
        if (SHUF) {
            int k = oc >> 2;
            int a = (oc >> 1) & 1;
            int bb = oc & 1;
            float* op = out + ((n * 100 + k) * 256 + (yy * 2 + a)) * 256 + bb;
            #pragma unroll
            for (int q = 0; q < 8; q++) {
                float v0, v1;
                upk2(acc[o][q], v0, v1);
                v0 += bv; v1 += bv;
                if (RELU) { v0 = fmaxf(v0, 0.f); v1 = fmaxf(v1, 0.f); }
                op[(x0 + 2 * q)     * 2] = v0;
                op[(x0 + 2 * q + 1) * 2] = v1;
            }
        } else {
            float* op = out + ((n * 64 + oc) * HH + yy) * WW + x0;
            const float* rp = RES ? res + ((n * 64 + oc) * HH + yy) * WW + x0 : nullptr;
            #pragma unroll
            for (int q = 0; q < 8; q++) {
                float v0, v1;
                upk2(acc[o][q], v0, v1);
                v0 += bv; v1 += bv;
                if (RELU) { v0 = fmaxf(v0, 0.f); v1 = fmaxf(v1, 0.f); }
                if (RES) {
                    float2 r2 = *(const float2*)(rp + 2 * q);
                    v0 += r2.x; v1 += r2.y;
                }
                float2 v; v.x = v0; v.y = v1;
                *(float2*)(op + 2 * q) = v;
            }
        }
    }
}

// ---------------------------------------------------------------------------
// Tail: y = conv3x3(shuffled, out_w) + out_b + mean    (100 -> 3, 256x256)
// ---------------------------------------------------------------------------
__global__ __launch_bounds__(256) void tail_kernel(
    const float* __restrict__ in, const float* __restrict__ w,
    const float* __restrict__ b, float* __restrict__ out)
{
    __shared__ float w_s[2700];
    for (int i = threadIdx.x; i < 2700; i += 256) w_s[i] = w[i];
    __syncthreads();

    int idx = blockIdx.x * 256 + threadIdx.x;
    int x = idx & 255;
    int y = (idx >> 8) & 255;
    int n = idx >> 16;

    float a0 = b[0], a1 = b[1], a2 = b[2];
    for (int ic = 0; ic < 100; ic++) {
        const float* ip = in + ((n * 100 + ic) * 256) * 256;
        #pragma unroll
        for (int dy = 0; dy < 3; dy++) {
            int gy = y + dy - 1;
            if ((unsigned)gy >= 256) continue;
            #pragma unroll
            for (int dx = 0; dx < 3; dx++) {
                int gx = x + dx - 1;
                if ((unsigned)gx >= 256) continue;
                float v = ip[gy * 256 + gx];
                int t = ic * 9 + dy * 3 + dx;
                a0 += v * w_s[t];
                a1 += v * w_s[900 + t];
                a2 += v * w_s[1800 + t];
            }
        }
    }
    const float m0 = 0.4488f * 255.0f, m1 = 0.4371f * 255.0f, m2 = 0.404f * 255.0f;
    out[((n * 3 + 0) * 256 + y) * 256 + x] = a0 + m0;
    out[((n * 3 + 1) * 256 + y) * 256 + x] = a1 + m1;
    out[((n * 3 + 2) * 256 + y) * 256 + x] = a2 + m2;
}

// ---------------------------------------------------------------------------
extern "C" void kernel_launch(void* const* d_in, const int* in_sizes, int n_in,
                              void* d_out, int out_size)
{
    const float* x       = (const float*)d_in[0];
    const float* head_w  = (const float*)d_in[1];
    const float* head_b  = (const float*)d_in[2];
    const float* rb_w1   = (const float*)d_in[3];
    const float* rb_b1   = (const float*)d_in[4];
    const float* rb_w2   = (const float*)d_in[5];
    const float* rb_b2   = (const float*)d_in[6];
    const float* body_w  = (const float*)d_in[7];
    const float* body_b  = (const float*)d_in[8];
    const float* super_w = (const float*)d_in[9];
    const float* super_b = (const float*)d_in[10];
    const float* out_w   = (const float*)d_in[11];
    const float* out_b   = (const float*)d_in[12];
    float* out = (float*)d_out;

    float *pH, *pA, *pB, *pS, *pW1, *pW2, *pWB, *pWS;
    cudaGetSymbolAddress((void**)&pH, g_H);
    cudaGetSymbolAddress((void**)&pA, g_A);
    cudaGetSymbolAddress((void**)&pB, g_B);
    cudaGetSymbolAddress((void**)&pS, g_S);
    cudaGetSymbolAddress((void**)&pW1, g_W1);
    cudaGetSymbolAddress((void**)&pW2, g_W2);
    cudaGetSymbolAddress((void**)&pWB, g_WB);
    cudaGetSymbolAddress((void**)&pWS, g_WS);

    // weight reformat (tiny)
    dim3 rg(144, 1, 16);
    reformat_w<<<rg, 256>>>(rb_w1, pW1, 64, 64 * 64 * 9);
    reformat_w<<<rg, 256>>>(rb_w2, pW2, 64, 64 * 64 * 9);
    reformat_w<<<dim3(144, 1, 1), 256>>>(body_w, pWB, 64, 0);
    reformat_w<<<dim3(144, 7, 1), 256>>>(super_w, pWS, 400, 0);

    // head
    head_kernel<<<(N_IMG * CF * HH * WW) / 256, 256>>>(x, head_w, head_b, pH);

    dim3 grid(WW / 16, HH / 8, N_IMG);

    // 16 residual blocks: B = relu(conv1(cur)); A = cur + conv2(B)
    const float* cur = pH;
    for (int i = 0; i < 16; i++) {
        conv3x3_64<true, false, false><<<grid, 128>>>(
            cur, pW1 + (size_t)i * WCHUNK, rb_b1 + i * 64, nullptr, pB, 64, 1);
        conv3x3_64<false, true, false><<<grid, 128>>>(
            pB, pW2 + (size_t)i * WCHUNK, rb_b2 + i * 64, cur, pA, 64, 1);
        cur = pA;
    }

    // body: H = conv(A) + H
    conv3x3_64<false, true, false><<<grid, 128>>>(pA, pWB, body_b, pH, pH, 64, 1);

    // super conv 64 -> 400 with fused pixel shuffle (7 oc-chunks of 64)
    dim3 gridS(WW / 16, HH / 8, N_IMG * 7);
    conv3x3_64<false, false, true><<<gridS, 128>>>(pH, pWS, super_b, nullptr, pS, 400, 7);

    // tail conv 100 -> 3 on 256x256 + add mean
    tail_kernel<<<(N_IMG * 256 * 256) / 256, 256>>>(pS, out_w, out_b, out);
}